// round 15
// baseline (speedup 1.0000x reference)
#include <cuda_runtime.h>
#include <cuda_fp16.h>
#include <stdint.h>
#include <math.h>

// ---------------- problem constants ----------------
#define BQ     2
#define TT     8
#define HDIM   64
#define WDIM   64
#define CC     192
#define HEADS  6
#define DH     32
#define NTOK   256
#define NWIN   128
#define BWIN   256
#define MROWS  65536
#define HID    768
#define CPB_M  1575
#define CPB_H  512
#define L2E    1.4426950408889634f

typedef unsigned long long ull;

// ---------------- scratch ----------------
__device__ __half g_xh [MROWS * CC];       // gathered input, fp16, window layout (qkv A)
__device__ float  g_qkv[MROWS * 3 * CC];   // qkv (fp32, attention reads)
__device__ __half g_xw [MROWS * CC];       // attention output fp16 (proj A)
__device__ float  g_pr [MROWS * CC];       // proj / fc2 out (fp32, LN reads)
__device__ float  g_x1 [MROWS * CC];       // attn residual fp32 (final residual)
__device__ __half g_x1h[MROWS * CC];       // fp16 copy (fc1 A)
__device__ __half g_h1 [MROWS * HID];      // MLP hidden fp16 (fc2 A)
__device__ __half g_wqkv[3 * CC * CC];
__device__ __half g_wproj[CC * CC];
__device__ __half g_wfc1[HID * CC];
__device__ __half g_wfc2[CC * HID];
__device__ float  g_tbl[CPB_M * HEADS];
__device__ float  g_scale[HEADS];

__device__ __forceinline__ float ex2f(float x) {
    float r;
    asm("ex2.approx.f32 %0, %1;" : "=f"(r) : "f"(x));
    return r;
}

// window row -> source row in (B,T,H,W) layout
__device__ __forceinline__ long src_row(int r) {
    int b_ = r >> 8, n = r & 255;
    int bb = b_ >> 7, w_ = b_ & 127;
    int wt = w_ >> 6, wh = (w_ >> 3) & 7, ww = w_ & 7;
    int it = n >> 6, ih = (n >> 3) & 7, iw = n & 7;
    int t = (wt * 4 + it + 2) & 7;
    int h = (wh * 8 + ih + 4) & 63;
    int w = (ww * 8 + iw + 4) & 63;
    return (long)(((bb * TT + t) * HDIM + h) * WDIM + w);
}

// ---------------- weight fp32 -> fp16 ----------------
__global__ void conv_kernel(const float* __restrict__ in, __half* __restrict__ out, int n) {
    int i = blockIdx.x * 256 + threadIdx.x;
    if (i < n) out[i] = __float2half_rn(in[i]);
}

// ---------------- gather + fp16 convert (window layout) ----------------
__global__ void gatherh_kernel(const float* __restrict__ x) {
    int idx = blockIdx.x * 256 + threadIdx.x;    // over MROWS*24 uint4 units
    int r = idx / 24, c8 = idx % 24;
    long src = src_row(r) * CC + c8 * 8;
    float4 v0 = *(const float4*)&x[src];
    float4 v1 = *(const float4*)&x[src + 4];
    __half2 h[4];
    h[0] = __floats2half2_rn(v0.x, v0.y);
    h[1] = __floats2half2_rn(v0.z, v0.w);
    h[2] = __floats2half2_rn(v1.x, v1.y);
    h[3] = __floats2half2_rn(v1.z, v1.w);
    *(uint4*)&g_xh[(long)r * CC + c8 * 8] = *(uint4*)h;
}

// ---------------- CPB table ----------------
__global__ void cpb_kernel(const float* __restrict__ w1, const float* __restrict__ b1,
                           const float* __restrict__ w2, const float* __restrict__ ls) {
    int m = blockIdx.x;
    int tid = threadIdx.x;
    if (m == 0 && tid < HEADS)
        g_scale[tid] = expf(fminf(ls[tid], logf(100.0f)));

    int i = m / 225, rem = m % 225, j = rem / 15, k = rem % 15;
    float v0 = (float)(i - 3) * (8.0f / 3.0f);
    float v1 = (float)(j - 7) * (8.0f / 7.0f);
    float v2 = (float)(k - 7) * (8.0f / 7.0f);
    const float inv_l8 = 1.0f / log2f(8.0f);
    float c0 = copysignf(log2f(fabsf(v0) + 1.0f) * inv_l8, v0);
    float c1 = copysignf(log2f(fabsf(v1) + 1.0f) * inv_l8, v1);
    float c2 = copysignf(log2f(fabsf(v2) + 1.0f) * inv_l8, v2);

    float h = c0 * w1[tid * 3 + 0] + c1 * w1[tid * 3 + 1] + c2 * w1[tid * 3 + 2] + b1[tid];
    h = fmaxf(h, 0.0f);

    __shared__ float red[CPB_H];
    for (int hh = 0; hh < HEADS; hh++) {
        red[tid] = h * w2[hh * CPB_H + tid];
        __syncthreads();
        for (int s = CPB_H / 2; s > 0; s >>= 1) {
            if (tid < s) red[tid] += red[tid + s];
            __syncthreads();
        }
        if (tid == 0) {
            float t = red[0];
            g_tbl[m * HEADS + hh] = 16.0f / (1.0f + expf(-t));
        }
        __syncthreads();
    }
}

// ---------------- helpers ----------------
__device__ __forceinline__ uint32_t f2tf32(float f) {
    uint32_t u;
    asm("cvt.rna.tf32.f32 %0, %1;" : "=r"(u) : "f"(f));
    return u;
}
__device__ __forceinline__ uint32_t s2u(const void* p) {
    uint32_t a;
    asm("{ .reg .u64 t; cvta.to.shared.u64 t, %1; cvt.u32.u64 %0, t; }" : "=r"(a) : "l"(p));
    return a;
}

#define MMA_F16(acc, af, bf)                                               \
    asm volatile(                                                          \
        "mma.sync.aligned.m16n8k16.row.col.f32.f16.f16.f32 "               \
        "{%0,%1,%2,%3}, {%4,%5,%6,%7}, {%8,%9}, {%0,%1,%2,%3};\n"          \
        : "+f"(acc[0]), "+f"(acc[1]), "+f"(acc[2]), "+f"(acc[3])           \
        : "r"(af[0]), "r"(af[1]), "r"(af[2]), "r"(af[3]),                  \
          "r"(bf[0]), "r"(bf[1]))

#define MMA_TF32(acc, af, bf)                                              \
    asm volatile(                                                          \
        "mma.sync.aligned.m16n8k8.row.col.f32.tf32.tf32.f32 "              \
        "{%0,%1,%2,%3}, {%4,%5,%6,%7}, {%8,%9}, {%0,%1,%2,%3};\n"          \
        : "+f"(acc[0]), "+f"(acc[1]), "+f"(acc[2]), "+f"(acc[3])           \
        : "r"(af[0]), "r"(af[1]), "r"(af[2]), "r"(af[3]),                  \
          "r"(bf[0]), "r"(bf[1]))

#define LDSM_X4(r0, r1, r2, r3, addr)                                      \
    asm volatile("ldmatrix.sync.aligned.m8n8.x4.shared.b16 "               \
                 "{%0,%1,%2,%3}, [%4];"                                    \
                 : "=r"(r0), "=r"(r1), "=r"(r2), "=r"(r3) : "r"(addr))

// ---------------- fp16 GEMM: 256x64 CTA, 8 warps x (64x32 warp tile), BK=16, 2-stage, LDSM ----------------
// A and W are fp16 in gmem (no in-kernel conversion).
template <int ACT, bool OUTHALF>
__device__ __forceinline__ void gemm_tc_body(const __half* __restrict__ A, const __half* __restrict__ Wt,
                                             const float* __restrict__ bias, void* __restrict__ Cm,
                                             int Nn, int K) {
    __shared__ uint32_t As[2][256][12];
    __shared__ uint32_t Bs[2][64][12];

    int tid = threadIdx.x;        // 0..255
    int lane = tid & 31;
    int warp = tid >> 5;          // 0..7
    int wm = warp >> 1;           // 0..3 -> M offset wm*64
    int wn = warp & 1;            // 0..1 -> N offset wn*32
    int m0 = blockIdx.y * 256;
    int n0 = blockIdx.x * 64;

    int grp = lane >> 2;          // 0..7
    int kc  = lane & 3;           // 0..3

    // global->smem: A rows split in 2 half-chunks of 8 halves (16B)
    int rA0 = tid >> 1,          hA = (tid & 1) * 8;     // halves offset 0/8
    int rA1 = (tid + 256) >> 1;                          // same hA
    int uA  = (tid & 1) * 4;                             // uint col 0/4
    long a0 = (long)(m0 + rA0) * K;
    long a1 = (long)(m0 + rA1) * K;
    bool doB = tid < 128;
    int rB = tid >> 1, hB = (tid & 1) * 8, uB = (tid & 1) * 4;
    long bb = (long)(n0 + rB) * K;

    // LDSM lane addresses (per stage)
    uint32_t aaddr[2][4], baddr[2][2];
    #pragma unroll
    for (int st = 0; st < 2; st++) {
        #pragma unroll
        for (int mt = 0; mt < 4; mt++) {
            int r = wm * 64 + mt * 16 + (lane & 15);
            aaddr[st][mt] = s2u(&As[st][r][(lane >> 4) * 4]);
        }
        #pragma unroll
        for (int bt = 0; bt < 2; bt++) {
            int c = wn * 32 + bt * 16 + ((lane >> 4) << 3) + (lane & 7);
            baddr[st][bt] = s2u(&Bs[st][c][((lane >> 3) & 1) * 4]);
        }
    }

    float acc[4][4][4];
    #pragma unroll
    for (int i = 0; i < 4; i++)
        #pragma unroll
        for (int j = 0; j < 4; j++)
            #pragma unroll
            for (int q = 0; q < 4; q++) acc[i][j][q] = 0.0f;

    int nT = K / 16;
    uint4 pa0, pa1, pb;
    pa0 = *(const uint4*)&A[a0 + hA];
    pa1 = *(const uint4*)&A[a1 + hA];
    if (doB) pb = *(const uint4*)&Wt[bb + hB];

    // store stage 0
    *(uint4*)&As[0][rA0][uA] = pa0;
    *(uint4*)&As[0][rA1][uA] = pa1;
    if (doB) *(uint4*)&Bs[0][rB][uB] = pb;

    for (int k = 0; k < nT; k++) {
        if (k + 1 < nT) {
            int kn = (k + 1) * 16;
            pa0 = *(const uint4*)&A[a0 + kn + hA];
            pa1 = *(const uint4*)&A[a1 + kn + hA];
            if (doB) pb = *(const uint4*)&Wt[bb + kn + hB];
        }
        __syncthreads();
        int st = k & 1;

        uint32_t af[4][4];
        #pragma unroll
        for (int mt = 0; mt < 4; mt++)
            LDSM_X4(af[mt][0], af[mt][1], af[mt][2], af[mt][3], aaddr[st][mt]);
        uint32_t bf[4][2];
        #pragma unroll
        for (int bt = 0; bt < 2; bt++) {
            uint32_t r0, r1, r2, r3;
            LDSM_X4(r0, r1, r2, r3, baddr[st][bt]);
            bf[bt * 2 + 0][0] = r0; bf[bt * 2 + 0][1] = r1;
            bf[bt * 2 + 1][0] = r2; bf[bt * 2 + 1][1] = r3;
        }
        #pragma unroll
        for (int mt = 0; mt < 4; mt++)
            #pragma unroll
            for (int nt = 0; nt < 4; nt++)
                MMA_F16(acc[mt][nt], af[mt], bf[nt]);

        if (k + 1 < nT) {
            int sn = (k + 1) & 1;
            *(uint4*)&As[sn][rA0][uA] = pa0;
            *(uint4*)&As[sn][rA1][uA] = pa1;
            if (doB) *(uint4*)&Bs[sn][rB][uB] = pb;
        }
    }

    #pragma unroll
    for (int mt = 0; mt < 4; mt++) {
        int row = m0 + wm * 64 + mt * 16 + grp;
        #pragma unroll
        for (int nt = 0; nt < 4; nt++) {
            int col = n0 + wn * 32 + nt * 8 + kc * 2;
            float b0 = bias[col], b1 = bias[col + 1];
            float c0 = acc[mt][nt][0] + b0;
            float c1 = acc[mt][nt][1] + b1;
            float c2 = acc[mt][nt][2] + b0;
            float c3 = acc[mt][nt][3] + b1;
            if (ACT == 1) {
                c0 = 0.5f * c0 * (1.0f + erff(c0 * 0.70710678118654752f));
                c1 = 0.5f * c1 * (1.0f + erff(c1 * 0.70710678118654752f));
                c2 = 0.5f * c2 * (1.0f + erff(c2 * 0.70710678118654752f));
                c3 = 0.5f * c3 * (1.0f + erff(c3 * 0.70710678118654752f));
            }
            if (OUTHALF) {
                __half* C = (__half*)Cm;
                *(__half2*)&C[(long)row * Nn + col] = __floats2half2_rn(c0, c1);
                *(__half2*)&C[(long)(row + 8) * Nn + col] = __floats2half2_rn(c2, c3);
            } else {
                float* C = (float*)Cm;
                *(float2*)&C[(long)row * Nn + col] = make_float2(c0, c1);
                *(float2*)&C[(long)(row + 8) * Nn + col] = make_float2(c2, c3);
            }
        }
    }
}

__global__ void __launch_bounds__(256, 2) gemm_qkv_k (const float* b) { gemm_tc_body<0, false>(g_xh,  g_wqkv,  b, g_qkv, 3 * CC, CC); }
__global__ void __launch_bounds__(256, 2) gemm_proj_k(const float* b) { gemm_tc_body<0, false>(g_xw,  g_wproj, b, g_pr,  CC,     CC); }
__global__ void __launch_bounds__(256, 2) gemm_fc1_k (const float* b) { gemm_tc_body<1, true >(g_x1h, g_wfc1,  b, g_h1,  HID,    CC); }
__global__ void __launch_bounds__(256, 2) gemm_fc2_k (const float* b) { gemm_tc_body<0, false>(g_h1,  g_wfc2,  b, g_pr,  CC,    HID); }

// ---------------- tensor-core windowed attention (output now fp16) ----------------
#define ATTN_SMEM 113312

__global__ void __launch_bounds__(256, 2) attn_kernel() {
    extern __shared__ char smraw[];
    uint32_t* ks  = (uint32_t*)smraw;
    float*    vs  = (float*)(smraw + 36864);
    float*    ps  = (float*)(smraw + 70144);
    float*    tblp = (float*)(smraw + 104960);
    uint32_t* jrs = (uint32_t*)(smraw + 111264);
    uint32_t* cjrs = (uint32_t*)(smraw + 112288);

    int b_ = blockIdx.x / HEADS;
    int hh = blockIdx.x % HEADS;
    int tid = threadIdx.x;
    int lane = tid & 31;
    int wid = tid >> 5;
    int grp = lane >> 2, kc = lane & 3;

    float scale_h = g_scale[hh];
    float Mh = scale_h + 16.0f;

    for (int i = tid; i < CPB_M; i += 256)
        tblp[i] = g_tbl[i * HEADS + hh] * L2E - Mh * L2E;
    if (tid == 0) tblp[CPB_M] = -1000.0f;

    {
        int n = tid;
        int w_ = b_ & 127;
        int wt = w_ >> 6, wh = (w_ >> 3) & 7, ww = w_ & 7;
        int it = n >> 6, ih = (n >> 3) & 7, iw = n & 7;
        int ts = wt * 4 + it, hs = wh * 8 + ih, wv = ww * 8 + iw;
        int dt = (ts < 4) ? 0 : (ts < 6 ? 1 : 2);
        int dh = (hs < 56) ? 0 : (hs < 60 ? 1 : 2);
        int dw = (wv < 56) ? 0 : (wv < 60 ? 1 : 2);
        uint32_t reg = (uint32_t)(dt * 9 + dh * 3 + dw);
        jrs[n]  = (uint32_t)(it * 225 + ih * 15 + iw) | (reg << 20);
        cjrs[n] = (uint32_t)((it + 3) * 225 + (ih + 7) * 15 + (iw + 7)) | (reg << 20);
    }

    {
        int key = tid;
        long base = ((long)b_ * NTOK + key) * (3 * CC) + hh * DH;
        const float4* kp4 = (const float4*)&g_qkv[base + CC];
        const float4* vp4 = (const float4*)&g_qkv[base + 2 * CC];
        float4 kv[8];
        float ss = 0.0f;
        #pragma unroll
        for (int f = 0; f < 8; f++) {
            kv[f] = kp4[f];
            ss += kv[f].x * kv[f].x + kv[f].y * kv[f].y + kv[f].z * kv[f].z + kv[f].w * kv[f].w;
        }
        float rn = 1.0f / fmaxf(sqrtf(ss), 1e-12f);
        #pragma unroll
        for (int f = 0; f < 8; f++) {
            ks[key * 36 + f * 4 + 0] = f2tf32(kv[f].x * rn);
            ks[key * 36 + f * 4 + 1] = f2tf32(kv[f].y * rn);
            ks[key * 36 + f * 4 + 2] = f2tf32(kv[f].z * rn);
            ks[key * 36 + f * 4 + 3] = f2tf32(kv[f].w * rn);
        }
        #pragma unroll
        for (int f = 0; f < 8; f++) {
            float4 v = vp4[f];
            vs[(f * 4 + 0) * 260 + key] = v.x;
            vs[(f * 4 + 1) * 260 + key] = v.y;
            vs[(f * 4 + 2) * 260 + key] = v.z;
            vs[(f * 4 + 3) * 260 + key] = v.w;
        }
    }
    __syncthreads();

    float* myps = ps + wid * (32 * 34);
    {
        long qb = ((long)b_ * NTOK + wid * 32 + lane) * (3 * CC) + hh * DH;
        const float4* qp4 = (const float4*)&g_qkv[qb];
        float4 qv[8];
        float ss = 0.0f;
        #pragma unroll
        for (int f = 0; f < 8; f++) {
            qv[f] = qp4[f];
            ss += qv[f].x * qv[f].x + qv[f].y * qv[f].y + qv[f].z * qv[f].z + qv[f].w * qv[f].w;
        }
        float rn = scale_h / fmaxf(sqrtf(ss), 1e-12f);
        #pragma unroll
        for (int f = 0; f < 8; f++) {
            myps[lane * 34 + f * 4 + 0] = qv[f].x * rn;
            myps[lane * 34 + f * 4 + 1] = qv[f].y * rn;
            myps[lane * 34 + f * 4 + 2] = qv[f].z * rn;
            myps[lane * 34 + f * 4 + 3] = qv[f].w * rn;
        }
    }
    __syncwarp();
    uint32_t qa[2][4][4];
    #pragma unroll
    for (int mt = 0; mt < 2; mt++)
        #pragma unroll
        for (int kt = 0; kt < 4; kt++) {
            int r0 = mt * 16 + grp, c0 = kt * 8 + kc;
            qa[mt][kt][0] = f2tf32(myps[r0 * 34 + c0]);
            qa[mt][kt][1] = f2tf32(myps[(r0 + 8) * 34 + c0]);
            qa[mt][kt][2] = f2tf32(myps[r0 * 34 + c0 + 4]);
            qa[mt][kt][3] = f2tf32(myps[(r0 + 8) * 34 + c0 + 4]);
        }
    __syncwarp();

    uint32_t mycjr[4];
    #pragma unroll
    for (int i = 0; i < 4; i++)
        mycjr[i] = cjrs[wid * 32 + ((i >> 1) * 16 + (i & 1) * 8 + grp)];

    float denom[4] = {0.0f, 0.0f, 0.0f, 0.0f};
    float oacc[2][4][4];
    #pragma unroll
    for (int mt = 0; mt < 2; mt++)
        #pragma unroll
        for (int nt = 0; nt < 4; nt++)
            #pragma unroll
            for (int q = 0; q < 4; q++) oacc[mt][nt][q] = 0.0f;

    for (int ch = 0; ch < 8; ch++) {
        int n0 = ch * 32;
        float s[2][4][4];
        #pragma unroll
        for (int mt = 0; mt < 2; mt++)
            #pragma unroll
            for (int nt = 0; nt < 4; nt++)
                #pragma unroll
                for (int q = 0; q < 4; q++) s[mt][nt][q] = 0.0f;
        #pragma unroll
        for (int kt = 0; kt < 4; kt++) {
            uint32_t kb[4][2];
            #pragma unroll
            for (int nt = 0; nt < 4; nt++) {
                int krow = n0 + nt * 8 + grp;
                kb[nt][0] = ks[krow * 36 + kt * 8 + kc];
                kb[nt][1] = ks[krow * 36 + kt * 8 + kc + 4];
            }
            #pragma unroll
            for (int mt = 0; mt < 2; mt++)
                #pragma unroll
                for (int nt = 0; nt < 4; nt++)
                    MMA_TF32(s[mt][nt], qa[mt][kt], kb[nt]);
        }
        #pragma unroll
        for (int nt = 0; nt < 4; nt++) {
            int k0 = n0 + nt * 8 + 2 * kc;
            uint32_t jr0 = jrs[k0], jr1 = jrs[k0 + 1];
            #pragma unroll
            for (int mt = 0; mt < 2; mt++)
                #pragma unroll
                for (int h = 0; h < 2; h++) {
                    uint32_t mj = mycjr[mt * 2 + h];
                    uint32_t d0 = mj - jr0, x0 = mj ^ jr0;
                    uint32_t d1 = mj - jr1, x1 = mj ^ jr1;
                    int i0 = (x0 < (1u << 20)) ? (int)(d0 & 0xFFFFFu) : CPB_M;
                    int i1 = (x1 < (1u << 20)) ? (int)(d1 & 0xFFFFFu) : CPB_M;
                    float p0 = ex2f(s[mt][nt][h * 2 + 0] * L2E + tblp[i0]);
                    float p1 = ex2f(s[mt][nt][h * 2 + 1] * L2E + tblp[i1]);
                    denom[mt * 2 + h] += p0 + p1;
                    int row = mt * 16 + h * 8 + grp;
                    *(float2*)&myps[row * 34 + nt * 8 + 2 * kc] = make_float2(p0, p1);
                }
        }
        __syncwarp();
        #pragma unroll
        for (int kt = 0; kt < 4; kt++) {
            uint32_t pa[2][4], vb[4][2];
            #pragma unroll
            for (int mt = 0; mt < 2; mt++) {
                int r0 = mt * 16 + grp, c0 = kt * 8 + kc;
                pa[mt][0] = __float_as_uint(myps[r0 * 34 + c0]);
                pa[mt][1] = __float_as_uint(myps[(r0 + 8) * 34 + c0]);
                pa[mt][2] = __float_as_uint(myps[r0 * 34 + c0 + 4]);
                pa[mt][3] = __float_as_uint(myps[(r0 + 8) * 34 + c0 + 4]);
            }
            #pragma unroll
            for (int nt = 0; nt < 4; nt++) {
                vb[nt][0] = __float_as_uint(vs[(nt * 8 + grp) * 260 + n0 + kt * 8 + kc]);
                vb[nt][1] = __float_as_uint(vs[(nt * 8 + grp) * 260 + n0 + kt * 8 + kc + 4]);
            }
            #pragma unroll
            for (int mt = 0; mt < 2; mt++)
                #pragma unroll
                for (int nt = 0; nt < 4; nt++)
                    MMA_TF32(oacc[mt][nt], pa[mt], vb[nt]);
        }
        __syncwarp();
    }

    #pragma unroll
    for (int i = 0; i < 4; i++) {
        denom[i] += __shfl_xor_sync(0xffffffffu, denom[i], 1);
        denom[i] += __shfl_xor_sync(0xffffffffu, denom[i], 2);
        denom[i] = 1.0f / denom[i];
    }
    long ob = ((long)b_ * NTOK + wid * 32) * CC + hh * DH;
    #pragma unroll
    for (int mt = 0; mt < 2; mt++)
        #pragma unroll
        for (int nt = 0; nt < 4; nt++) {
            int r0 = mt * 16 + grp, c0 = nt * 8 + 2 * kc;
            float rd0 = denom[mt * 2 + 0], rd1 = denom[mt * 2 + 1];
            *(__half2*)&g_xw[ob + (long)r0 * CC + c0] =
                __floats2half2_rn(oacc[mt][nt][0] * rd0, oacc[mt][nt][1] * rd0);
            *(__half2*)&g_xw[ob + (long)(r0 + 8) * CC + c0] =
                __floats2half2_rn(oacc[mt][nt][2] * rd1, oacc[mt][nt][3] * rd1);
        }
}

// ---------------- LN(proj) + residual scatter (fp32 + fp16 copy) ----------------
__global__ void attn_post_kernel(const float* __restrict__ x,
                                 const float* __restrict__ g, const float* __restrict__ b) {
    int r = blockIdx.x;
    int c = threadIdx.x;
    float v = g_pr[(long)r * CC + c];
    float s1 = v, s2 = v * v;
    #pragma unroll
    for (int o = 16; o; o >>= 1) {
        s1 += __shfl_xor_sync(0xffffffffu, s1, o);
        s2 += __shfl_xor_sync(0xffffffffu, s2, o);
    }
    __shared__ float p1[6], p2[6];
    int w = c >> 5;
    if ((c & 31) == 0) { p1[w] = s1; p2[w] = s2; }
    __syncthreads();
    s1 = p1[0] + p1[1] + p1[2] + p1[3] + p1[4] + p1[5];
    s2 = p2[0] + p2[1] + p2[2] + p2[3] + p2[4] + p2[5];
    float mean = s1 * (1.0f / CC);
    float var = s2 * (1.0f / CC) - mean * mean;
    float ln = (v - mean) * rsqrtf(var + 1e-5f) * g[c] + b[c];
    long dst = src_row(r) * CC + c;
    float res = x[dst] + ln;
    g_x1[dst] = res;
    g_x1h[dst] = __float2half_rn(res);
}

// ---------------- final LN(fc2) + residual -> output ----------------
__global__ void final_kernel(float* __restrict__ out,
                             const float* __restrict__ g, const float* __restrict__ b) {
    int r = blockIdx.x;
    int c = threadIdx.x;
    float v = g_pr[(long)r * CC + c];
    float s1 = v, s2 = v * v;
    #pragma unroll
    for (int o = 16; o; o >>= 1) {
        s1 += __shfl_xor_sync(0xffffffffu, s1, o);
        s2 += __shfl_xor_sync(0xffffffffu, s2, o);
    }
    __shared__ float p1[6], p2[6];
    int w = c >> 5;
    if ((c & 31) == 0) { p1[w] = s1; p2[w] = s2; }
    __syncthreads();
    s1 = p1[0] + p1[1] + p1[2] + p1[3] + p1[4] + p1[5];
    s2 = p2[0] + p2[1] + p2[2] + p2[3] + p2[4] + p2[5];
    float mean = s1 * (1.0f / CC);
    float var = s2 * (1.0f / CC) - mean * mean;
    float ln = (v - mean) * rsqrtf(var + 1e-5f) * g[c] + b[c];
    out[(long)r * CC + c] = g_x1[(long)r * CC + c] + ln;
}

// ---------------- launch ----------------
extern "C" void kernel_launch(void* const* d_in, const int* in_sizes, int n_in,
                              void* d_out, int out_size) {
    const float* x      = (const float*)d_in[0];
    const float* qkv_w  = (const float*)d_in[1];
    const float* qkv_b  = (const float*)d_in[2];
    const float* proj_w = (const float*)d_in[3];
    const float* proj_b = (const float*)d_in[4];
    const float* cpb_w1 = (const float*)d_in[5];
    const float* cpb_b1 = (const float*)d_in[6];
    const float* cpb_w2 = (const float*)d_in[7];
    const float* ls     = (const float*)d_in[8];
    const float* n1g    = (const float*)d_in[9];
    const float* n1b    = (const float*)d_in[10];
    const float* n2g    = (const float*)d_in[11];
    const float* n2b    = (const float*)d_in[12];
    const float* fc1_w  = (const float*)d_in[13];
    const float* fc1_b  = (const float*)d_in[14];
    const float* fc2_w  = (const float*)d_in[15];
    const float* fc2_b  = (const float*)d_in[16];
    float* out = (float*)d_out;

    cudaFuncSetAttribute(attn_kernel, cudaFuncAttributeMaxDynamicSharedMemorySize, ATTN_SMEM);

    __half* wq; cudaGetSymbolAddress((void**)&wq, g_wqkv);
    __half* wp; cudaGetSymbolAddress((void**)&wp, g_wproj);
    __half* w1; cudaGetSymbolAddress((void**)&w1, g_wfc1);
    __half* w2; cudaGetSymbolAddress((void**)&w2, g_wfc2);

    conv_kernel<<<(3 * CC * CC + 255) / 256, 256>>>(qkv_w, wq, 3 * CC * CC);
    conv_kernel<<<(CC * CC + 255) / 256, 256>>>(proj_w, wp, CC * CC);
    conv_kernel<<<(HID * CC + 255) / 256, 256>>>(fc1_w, w1, HID * CC);
    conv_kernel<<<(CC * HID + 255) / 256, 256>>>(fc2_w, w2, CC * HID);
    gatherh_kernel<<<(MROWS * 24) / 256, 256>>>(x);
    cpb_kernel<<<CPB_M, CPB_H>>>(cpb_w1, cpb_b1, cpb_w2, ls);

    gemm_qkv_k<<<dim3((3 * CC) / 64, MROWS / 256), 256>>>(qkv_b);
    attn_kernel<<<BWIN * HEADS, 256, ATTN_SMEM>>>();
    gemm_proj_k<<<dim3(CC / 64, MROWS / 256), 256>>>(proj_b);
    attn_post_kernel<<<MROWS, 192>>>(x, n1g, n1b);
    gemm_fc1_k<<<dim3(HID / 64, MROWS / 256), 256>>>(fc1_b);
    gemm_fc2_k<<<dim3(CC / 64, MROWS / 256), 256>>>(fc2_b);
    final_kernel<<<MROWS, 192>>>(out, n2g, n2b);
}

// round 16
// speedup vs baseline: 1.0758x; 1.0758x over previous
#include <cuda_runtime.h>
#include <cuda_fp16.h>
#include <stdint.h>
#include <math.h>

// ---------------- problem constants ----------------
#define BQ     2
#define TT     8
#define HDIM   64
#define WDIM   64
#define CC     192
#define HEADS  6
#define DH     32
#define NTOK   256
#define NWIN   128
#define BWIN   256
#define MROWS  65536
#define HID    768
#define CPB_M  1575
#define CPB_H  512
#define L2E    1.4426950408889634f

typedef unsigned long long ull;

// ---------------- scratch ----------------
__device__ __half g_xh [MROWS * CC];       // gathered input, fp16, window layout (qkv A)
__device__ float  g_qkv[MROWS * 3 * CC];   // qkv (fp32, attention reads)
__device__ __half g_xw [MROWS * CC];       // attention output fp16 (proj A)
__device__ float  g_pr [MROWS * CC];       // proj / fc2 out (fp32, LN reads)
__device__ float  g_x1 [MROWS * CC];       // attn residual fp32 (final residual)
__device__ __half g_x1h[MROWS * CC];       // fp16 copy (fc1 A)
__device__ __half g_h1 [MROWS * HID];      // MLP hidden fp16 (fc2 A)
__device__ __half g_wqkv[3 * CC * CC];
__device__ __half g_wproj[CC * CC];
__device__ __half g_wfc1[HID * CC];
__device__ __half g_wfc2[CC * HID];
__device__ float  g_tbl[CPB_M * HEADS];
__device__ float  g_scale[HEADS];

__device__ __forceinline__ float ex2f(float x) {
    float r;
    asm("ex2.approx.f32 %0, %1;" : "=f"(r) : "f"(x));
    return r;
}

// window row -> source row in (B,T,H,W) layout
__device__ __forceinline__ long src_row(int r) {
    int b_ = r >> 8, n = r & 255;
    int bb = b_ >> 7, w_ = b_ & 127;
    int wt = w_ >> 6, wh = (w_ >> 3) & 7, ww = w_ & 7;
    int it = n >> 6, ih = (n >> 3) & 7, iw = n & 7;
    int t = (wt * 4 + it + 2) & 7;
    int h = (wh * 8 + ih + 4) & 63;
    int w = (ww * 8 + iw + 4) & 63;
    return (long)(((bb * TT + t) * HDIM + h) * WDIM + w);
}

// ---------------- weight fp32 -> fp16 ----------------
__global__ void conv_kernel(const float* __restrict__ in, __half* __restrict__ out, int n) {
    int i = blockIdx.x * 256 + threadIdx.x;
    if (i < n) out[i] = __float2half_rn(in[i]);
}

// ---------------- gather + fp16 convert (window layout) ----------------
__global__ void gatherh_kernel(const float* __restrict__ x) {
    int idx = blockIdx.x * 256 + threadIdx.x;    // over MROWS*24 uint4 units
    int r = idx / 24, c8 = idx % 24;
    long src = src_row(r) * CC + c8 * 8;
    float4 v0 = *(const float4*)&x[src];
    float4 v1 = *(const float4*)&x[src + 4];
    __half2 h[4];
    h[0] = __floats2half2_rn(v0.x, v0.y);
    h[1] = __floats2half2_rn(v0.z, v0.w);
    h[2] = __floats2half2_rn(v1.x, v1.y);
    h[3] = __floats2half2_rn(v1.z, v1.w);
    *(uint4*)&g_xh[(long)r * CC + c8 * 8] = *(uint4*)h;
}

// ---------------- CPB table ----------------
__global__ void cpb_kernel(const float* __restrict__ w1, const float* __restrict__ b1,
                           const float* __restrict__ w2, const float* __restrict__ ls) {
    int m = blockIdx.x;
    int tid = threadIdx.x;
    if (m == 0 && tid < HEADS)
        g_scale[tid] = expf(fminf(ls[tid], logf(100.0f)));

    int i = m / 225, rem = m % 225, j = rem / 15, k = rem % 15;
    float v0 = (float)(i - 3) * (8.0f / 3.0f);
    float v1 = (float)(j - 7) * (8.0f / 7.0f);
    float v2 = (float)(k - 7) * (8.0f / 7.0f);
    const float inv_l8 = 1.0f / log2f(8.0f);
    float c0 = copysignf(log2f(fabsf(v0) + 1.0f) * inv_l8, v0);
    float c1 = copysignf(log2f(fabsf(v1) + 1.0f) * inv_l8, v1);
    float c2 = copysignf(log2f(fabsf(v2) + 1.0f) * inv_l8, v2);

    float h = c0 * w1[tid * 3 + 0] + c1 * w1[tid * 3 + 1] + c2 * w1[tid * 3 + 2] + b1[tid];
    h = fmaxf(h, 0.0f);

    __shared__ float red[CPB_H];
    for (int hh = 0; hh < HEADS; hh++) {
        red[tid] = h * w2[hh * CPB_H + tid];
        __syncthreads();
        for (int s = CPB_H / 2; s > 0; s >>= 1) {
            if (tid < s) red[tid] += red[tid + s];
            __syncthreads();
        }
        if (tid == 0) {
            float t = red[0];
            g_tbl[m * HEADS + hh] = 16.0f / (1.0f + expf(-t));
        }
        __syncthreads();
    }
}

// ---------------- helpers ----------------
__device__ __forceinline__ uint32_t f2tf32(float f) {
    uint32_t u;
    asm("cvt.rna.tf32.f32 %0, %1;" : "=r"(u) : "f"(f));
    return u;
}
__device__ __forceinline__ uint32_t s2u(const void* p) {
    uint32_t a;
    asm("{ .reg .u64 t; cvta.to.shared.u64 t, %1; cvt.u32.u64 %0, t; }" : "=r"(a) : "l"(p));
    return a;
}

#define CP_ASYNC16(dst, src) \
    asm volatile("cp.async.cg.shared.global [%0], [%1], 16;" :: "r"(dst), "l"(src))
#define CP_COMMIT() asm volatile("cp.async.commit_group;" ::: "memory")
#define CP_WAIT1()  asm volatile("cp.async.wait_group 1;" ::: "memory")

#define MMA_F16(acc, af, bf)                                               \
    asm volatile(                                                          \
        "mma.sync.aligned.m16n8k16.row.col.f32.f16.f16.f32 "               \
        "{%0,%1,%2,%3}, {%4,%5,%6,%7}, {%8,%9}, {%0,%1,%2,%3};\n"          \
        : "+f"(acc[0]), "+f"(acc[1]), "+f"(acc[2]), "+f"(acc[3])           \
        : "r"(af[0]), "r"(af[1]), "r"(af[2]), "r"(af[3]),                  \
          "r"(bf[0]), "r"(bf[1]))

#define MMA_TF32(acc, af, bf)                                              \
    asm volatile(                                                          \
        "mma.sync.aligned.m16n8k8.row.col.f32.tf32.tf32.f32 "              \
        "{%0,%1,%2,%3}, {%4,%5,%6,%7}, {%8,%9}, {%0,%1,%2,%3};\n"          \
        : "+f"(acc[0]), "+f"(acc[1]), "+f"(acc[2]), "+f"(acc[3])           \
        : "r"(af[0]), "r"(af[1]), "r"(af[2]), "r"(af[3]),                  \
          "r"(bf[0]), "r"(bf[1]))

#define LDSM_X4(r0, r1, r2, r3, addr)                                      \
    asm volatile("ldmatrix.sync.aligned.m8n8.x4.shared.b16 "               \
                 "{%0,%1,%2,%3}, [%4];"                                    \
                 : "=r"(r0), "=r"(r1), "=r"(r2), "=r"(r3) : "r"(addr))

// ---------------- fp16 GEMM: 256x64 CTA, 8 warps x (64x32 warp tile), BK=16,
//                  3-stage cp.async pipeline, LDSM fragment loads ----------------
template <int ACT, bool OUTHALF>
__device__ __forceinline__ void gemm_tc_body(const __half* __restrict__ A, const __half* __restrict__ Wt,
                                             const float* __restrict__ bias, void* __restrict__ Cm,
                                             int Nn, int K) {
    __shared__ uint32_t As[3][256][12];   // 36 KB
    __shared__ uint32_t Bs[3][64][12];    //  9 KB

    int tid = threadIdx.x;        // 0..255
    int lane = tid & 31;
    int warp = tid >> 5;          // 0..7
    int wm = warp >> 1;           // 0..3 -> M offset wm*64
    int wn = warp & 1;            // 0..1 -> N offset wn*32
    int m0 = blockIdx.y * 256;
    int n0 = blockIdx.x * 64;

    int grp = lane >> 2;          // 0..7
    int kc  = lane & 3;           // 0..3

    // global->smem slots: A rows split in 2 half-chunks of 8 halves (16B)
    int rA0 = tid >> 1, hA = (tid & 1) * 8, uA = (tid & 1) * 4;
    int rA1 = rA0 + 128;
    long a0 = (long)(m0 + rA0) * K + hA;
    long a1 = (long)(m0 + rA1) * K + hA;
    bool doB = tid < 128;
    int rB = tid >> 1, hB = (tid & 1) * 8, uB = (tid & 1) * 4;
    long bb = (long)(n0 + rB) * K + hB;

    uint32_t aS0[3], aS1[3], bS[3];
    #pragma unroll
    for (int st = 0; st < 3; st++) {
        aS0[st] = s2u(&As[st][rA0][uA]);
        aS1[st] = s2u(&As[st][rA1][uA]);
        bS[st]  = s2u(&Bs[st][rB][uB]);
    }

    // LDSM lane addresses per stage
    uint32_t aaddr[3][4], baddr[3][2];
    #pragma unroll
    for (int st = 0; st < 3; st++) {
        #pragma unroll
        for (int mt = 0; mt < 4; mt++) {
            int r = wm * 64 + mt * 16 + (lane & 15);
            aaddr[st][mt] = s2u(&As[st][r][(lane >> 4) * 4]);
        }
        #pragma unroll
        for (int bt = 0; bt < 2; bt++) {
            int c = wn * 32 + bt * 16 + ((lane >> 4) << 3) + (lane & 7);
            baddr[st][bt] = s2u(&Bs[st][c][((lane >> 3) & 1) * 4]);
        }
    }

    float acc[4][4][4];
    #pragma unroll
    for (int i = 0; i < 4; i++)
        #pragma unroll
        for (int j = 0; j < 4; j++)
            #pragma unroll
            for (int q = 0; q < 4; q++) acc[i][j][q] = 0.0f;

    int nT = K / 16;

    // prologue: stages 0,1
    #pragma unroll
    for (int s = 0; s < 2; s++) {
        if (s < nT) {
            CP_ASYNC16(aS0[s], (const char*)(A + a0 + s * 16));
            CP_ASYNC16(aS1[s], (const char*)(A + a1 + s * 16));
            if (doB) CP_ASYNC16(bS[s], (const char*)(Wt + bb + s * 16));
        }
        CP_COMMIT();
    }

    for (int k = 0; k < nT; k++) {
        CP_WAIT1();
        __syncthreads();

        int kn = k + 2;
        if (kn < nT) {
            int sn = kn % 3;
            CP_ASYNC16(aS0[sn], (const char*)(A + a0 + kn * 16));
            CP_ASYNC16(aS1[sn], (const char*)(A + a1 + kn * 16));
            if (doB) CP_ASYNC16(bS[sn], (const char*)(Wt + bb + kn * 16));
        }
        CP_COMMIT();

        int st = k % 3;
        uint32_t af[4][4];
        #pragma unroll
        for (int mt = 0; mt < 4; mt++)
            LDSM_X4(af[mt][0], af[mt][1], af[mt][2], af[mt][3], aaddr[st][mt]);
        uint32_t bf[4][2];
        #pragma unroll
        for (int bt = 0; bt < 2; bt++) {
            uint32_t r0, r1, r2, r3;
            LDSM_X4(r0, r1, r2, r3, baddr[st][bt]);
            bf[bt * 2 + 0][0] = r0; bf[bt * 2 + 0][1] = r1;
            bf[bt * 2 + 1][0] = r2; bf[bt * 2 + 1][1] = r3;
        }
        #pragma unroll
        for (int mt = 0; mt < 4; mt++)
            #pragma unroll
            for (int nt = 0; nt < 4; nt++)
                MMA_F16(acc[mt][nt], af[mt], bf[nt]);
    }

    #pragma unroll
    for (int mt = 0; mt < 4; mt++) {
        int row = m0 + wm * 64 + mt * 16 + grp;
        #pragma unroll
        for (int nt = 0; nt < 4; nt++) {
            int col = n0 + wn * 32 + nt * 8 + kc * 2;
            float b0 = bias[col], b1 = bias[col + 1];
            float c0 = acc[mt][nt][0] + b0;
            float c1 = acc[mt][nt][1] + b1;
            float c2 = acc[mt][nt][2] + b0;
            float c3 = acc[mt][nt][3] + b1;
            if (ACT == 1) {
                c0 = 0.5f * c0 * (1.0f + erff(c0 * 0.70710678118654752f));
                c1 = 0.5f * c1 * (1.0f + erff(c1 * 0.70710678118654752f));
                c2 = 0.5f * c2 * (1.0f + erff(c2 * 0.70710678118654752f));
                c3 = 0.5f * c3 * (1.0f + erff(c3 * 0.70710678118654752f));
            }
            if (OUTHALF) {
                __half* C = (__half*)Cm;
                *(__half2*)&C[(long)row * Nn + col] = __floats2half2_rn(c0, c1);
                *(__half2*)&C[(long)(row + 8) * Nn + col] = __floats2half2_rn(c2, c3);
            } else {
                float* C = (float*)Cm;
                *(float2*)&C[(long)row * Nn + col] = make_float2(c0, c1);
                *(float2*)&C[(long)(row + 8) * Nn + col] = make_float2(c2, c3);
            }
        }
    }
}

__global__ void __launch_bounds__(256, 2) gemm_qkv_k (const float* b) { gemm_tc_body<0, false>(g_xh,  g_wqkv,  b, g_qkv, 3 * CC, CC); }
__global__ void __launch_bounds__(256, 2) gemm_proj_k(const float* b) { gemm_tc_body<0, false>(g_xw,  g_wproj, b, g_pr,  CC,     CC); }
__global__ void __launch_bounds__(256, 2) gemm_fc1_k (const float* b) { gemm_tc_body<1, true >(g_x1h, g_wfc1,  b, g_h1,  HID,    CC); }
__global__ void __launch_bounds__(256, 2) gemm_fc2_k (const float* b) { gemm_tc_body<0, false>(g_h1,  g_wfc2,  b, g_pr,  CC,    HID); }

// ---------------- tensor-core windowed attention (unchanged, fp16 output) ----------------
#define ATTN_SMEM 113312

__global__ void __launch_bounds__(256, 2) attn_kernel() {
    extern __shared__ char smraw[];
    uint32_t* ks  = (uint32_t*)smraw;
    float*    vs  = (float*)(smraw + 36864);
    float*    ps  = (float*)(smraw + 70144);
    float*    tblp = (float*)(smraw + 104960);
    uint32_t* jrs = (uint32_t*)(smraw + 111264);
    uint32_t* cjrs = (uint32_t*)(smraw + 112288);

    int b_ = blockIdx.x / HEADS;
    int hh = blockIdx.x % HEADS;
    int tid = threadIdx.x;
    int lane = tid & 31;
    int wid = tid >> 5;
    int grp = lane >> 2, kc = lane & 3;

    float scale_h = g_scale[hh];
    float Mh = scale_h + 16.0f;

    for (int i = tid; i < CPB_M; i += 256)
        tblp[i] = g_tbl[i * HEADS + hh] * L2E - Mh * L2E;
    if (tid == 0) tblp[CPB_M] = -1000.0f;

    {
        int n = tid;
        int w_ = b_ & 127;
        int wt = w_ >> 6, wh = (w_ >> 3) & 7, ww = w_ & 7;
        int it = n >> 6, ih = (n >> 3) & 7, iw = n & 7;
        int ts = wt * 4 + it, hs = wh * 8 + ih, wv = ww * 8 + iw;
        int dt = (ts < 4) ? 0 : (ts < 6 ? 1 : 2);
        int dh = (hs < 56) ? 0 : (hs < 60 ? 1 : 2);
        int dw = (wv < 56) ? 0 : (wv < 60 ? 1 : 2);
        uint32_t reg = (uint32_t)(dt * 9 + dh * 3 + dw);
        jrs[n]  = (uint32_t)(it * 225 + ih * 15 + iw) | (reg << 20);
        cjrs[n] = (uint32_t)((it + 3) * 225 + (ih + 7) * 15 + (iw + 7)) | (reg << 20);
    }

    {
        int key = tid;
        long base = ((long)b_ * NTOK + key) * (3 * CC) + hh * DH;
        const float4* kp4 = (const float4*)&g_qkv[base + CC];
        const float4* vp4 = (const float4*)&g_qkv[base + 2 * CC];
        float4 kv[8];
        float ss = 0.0f;
        #pragma unroll
        for (int f = 0; f < 8; f++) {
            kv[f] = kp4[f];
            ss += kv[f].x * kv[f].x + kv[f].y * kv[f].y + kv[f].z * kv[f].z + kv[f].w * kv[f].w;
        }
        float rn = 1.0f / fmaxf(sqrtf(ss), 1e-12f);
        #pragma unroll
        for (int f = 0; f < 8; f++) {
            ks[key * 36 + f * 4 + 0] = f2tf32(kv[f].x * rn);
            ks[key * 36 + f * 4 + 1] = f2tf32(kv[f].y * rn);
            ks[key * 36 + f * 4 + 2] = f2tf32(kv[f].z * rn);
            ks[key * 36 + f * 4 + 3] = f2tf32(kv[f].w * rn);
        }
        #pragma unroll
        for (int f = 0; f < 8; f++) {
            float4 v = vp4[f];
            vs[(f * 4 + 0) * 260 + key] = v.x;
            vs[(f * 4 + 1) * 260 + key] = v.y;
            vs[(f * 4 + 2) * 260 + key] = v.z;
            vs[(f * 4 + 3) * 260 + key] = v.w;
        }
    }
    __syncthreads();

    float* myps = ps + wid * (32 * 34);
    {
        long qb = ((long)b_ * NTOK + wid * 32 + lane) * (3 * CC) + hh * DH;
        const float4* qp4 = (const float4*)&g_qkv[qb];
        float4 qv[8];
        float ss = 0.0f;
        #pragma unroll
        for (int f = 0; f < 8; f++) {
            qv[f] = qp4[f];
            ss += qv[f].x * qv[f].x + qv[f].y * qv[f].y + qv[f].z * qv[f].z + qv[f].w * qv[f].w;
        }
        float rn = scale_h / fmaxf(sqrtf(ss), 1e-12f);
        #pragma unroll
        for (int f = 0; f < 8; f++) {
            myps[lane * 34 + f * 4 + 0] = qv[f].x * rn;
            myps[lane * 34 + f * 4 + 1] = qv[f].y * rn;
            myps[lane * 34 + f * 4 + 2] = qv[f].z * rn;
            myps[lane * 34 + f * 4 + 3] = qv[f].w * rn;
        }
    }
    __syncwarp();
    uint32_t qa[2][4][4];
    #pragma unroll
    for (int mt = 0; mt < 2; mt++)
        #pragma unroll
        for (int kt = 0; kt < 4; kt++) {
            int r0 = mt * 16 + grp, c0 = kt * 8 + kc;
            qa[mt][kt][0] = f2tf32(myps[r0 * 34 + c0]);
            qa[mt][kt][1] = f2tf32(myps[(r0 + 8) * 34 + c0]);
            qa[mt][kt][2] = f2tf32(myps[r0 * 34 + c0 + 4]);
            qa[mt][kt][3] = f2tf32(myps[(r0 + 8) * 34 + c0 + 4]);
        }
    __syncwarp();

    uint32_t mycjr[4];
    #pragma unroll
    for (int i = 0; i < 4; i++)
        mycjr[i] = cjrs[wid * 32 + ((i >> 1) * 16 + (i & 1) * 8 + grp)];

    float denom[4] = {0.0f, 0.0f, 0.0f, 0.0f};
    float oacc[2][4][4];
    #pragma unroll
    for (int mt = 0; mt < 2; mt++)
        #pragma unroll
        for (int nt = 0; nt < 4; nt++)
            #pragma unroll
            for (int q = 0; q < 4; q++) oacc[mt][nt][q] = 0.0f;

    for (int ch = 0; ch < 8; ch++) {
        int n0 = ch * 32;
        float s[2][4][4];
        #pragma unroll
        for (int mt = 0; mt < 2; mt++)
            #pragma unroll
            for (int nt = 0; nt < 4; nt++)
                #pragma unroll
                for (int q = 0; q < 4; q++) s[mt][nt][q] = 0.0f;
        #pragma unroll
        for (int kt = 0; kt < 4; kt++) {
            uint32_t kb[4][2];
            #pragma unroll
            for (int nt = 0; nt < 4; nt++) {
                int krow = n0 + nt * 8 + grp;
                kb[nt][0] = ks[krow * 36 + kt * 8 + kc];
                kb[nt][1] = ks[krow * 36 + kt * 8 + kc + 4];
            }
            #pragma unroll
            for (int mt = 0; mt < 2; mt++)
                #pragma unroll
                for (int nt = 0; nt < 4; nt++)
                    MMA_TF32(s[mt][nt], qa[mt][kt], kb[nt]);
        }
        #pragma unroll
        for (int nt = 0; nt < 4; nt++) {
            int k0 = n0 + nt * 8 + 2 * kc;
            uint32_t jr0 = jrs[k0], jr1 = jrs[k0 + 1];
            #pragma unroll
            for (int mt = 0; mt < 2; mt++)
                #pragma unroll
                for (int h = 0; h < 2; h++) {
                    uint32_t mj = mycjr[mt * 2 + h];
                    uint32_t d0 = mj - jr0, x0 = mj ^ jr0;
                    uint32_t d1 = mj - jr1, x1 = mj ^ jr1;
                    int i0 = (x0 < (1u << 20)) ? (int)(d0 & 0xFFFFFu) : CPB_M;
                    int i1 = (x1 < (1u << 20)) ? (int)(d1 & 0xFFFFFu) : CPB_M;
                    float p0 = ex2f(s[mt][nt][h * 2 + 0] * L2E + tblp[i0]);
                    float p1 = ex2f(s[mt][nt][h * 2 + 1] * L2E + tblp[i1]);
                    denom[mt * 2 + h] += p0 + p1;
                    int row = mt * 16 + h * 8 + grp;
                    *(float2*)&myps[row * 34 + nt * 8 + 2 * kc] = make_float2(p0, p1);
                }
        }
        __syncwarp();
        #pragma unroll
        for (int kt = 0; kt < 4; kt++) {
            uint32_t pa[2][4], vb[4][2];
            #pragma unroll
            for (int mt = 0; mt < 2; mt++) {
                int r0 = mt * 16 + grp, c0 = kt * 8 + kc;
                pa[mt][0] = __float_as_uint(myps[r0 * 34 + c0]);
                pa[mt][1] = __float_as_uint(myps[(r0 + 8) * 34 + c0]);
                pa[mt][2] = __float_as_uint(myps[r0 * 34 + c0 + 4]);
                pa[mt][3] = __float_as_uint(myps[(r0 + 8) * 34 + c0 + 4]);
            }
            #pragma unroll
            for (int nt = 0; nt < 4; nt++) {
                vb[nt][0] = __float_as_uint(vs[(nt * 8 + grp) * 260 + n0 + kt * 8 + kc]);
                vb[nt][1] = __float_as_uint(vs[(nt * 8 + grp) * 260 + n0 + kt * 8 + kc + 4]);
            }
            #pragma unroll
            for (int mt = 0; mt < 2; mt++)
                #pragma unroll
                for (int nt = 0; nt < 4; nt++)
                    MMA_TF32(oacc[mt][nt], pa[mt], vb[nt]);
        }
        __syncwarp();
    }

    #pragma unroll
    for (int i = 0; i < 4; i++) {
        denom[i] += __shfl_xor_sync(0xffffffffu, denom[i], 1);
        denom[i] += __shfl_xor_sync(0xffffffffu, denom[i], 2);
        denom[i] = 1.0f / denom[i];
    }
    long ob = ((long)b_ * NTOK + wid * 32) * CC + hh * DH;
    #pragma unroll
    for (int mt = 0; mt < 2; mt++)
        #pragma unroll
        for (int nt = 0; nt < 4; nt++) {
            int r0 = mt * 16 + grp, c0 = nt * 8 + 2 * kc;
            float rd0 = denom[mt * 2 + 0], rd1 = denom[mt * 2 + 1];
            *(__half2*)&g_xw[ob + (long)r0 * CC + c0] =
                __floats2half2_rn(oacc[mt][nt][0] * rd0, oacc[mt][nt][1] * rd0);
            *(__half2*)&g_xw[ob + (long)(r0 + 8) * CC + c0] =
                __floats2half2_rn(oacc[mt][nt][2] * rd1, oacc[mt][nt][3] * rd1);
        }
}

// ---------------- LN(proj) + residual scatter (fp32 + fp16 copy) ----------------
__global__ void attn_post_kernel(const float* __restrict__ x,
                                 const float* __restrict__ g, const float* __restrict__ b) {
    int r = blockIdx.x;
    int c = threadIdx.x;
    float v = g_pr[(long)r * CC + c];
    float s1 = v, s2 = v * v;
    #pragma unroll
    for (int o = 16; o; o >>= 1) {
        s1 += __shfl_xor_sync(0xffffffffu, s1, o);
        s2 += __shfl_xor_sync(0xffffffffu, s2, o);
    }
    __shared__ float p1[6], p2[6];
    int w = c >> 5;
    if ((c & 31) == 0) { p1[w] = s1; p2[w] = s2; }
    __syncthreads();
    s1 = p1[0] + p1[1] + p1[2] + p1[3] + p1[4] + p1[5];
    s2 = p2[0] + p2[1] + p2[2] + p2[3] + p2[4] + p2[5];
    float mean = s1 * (1.0f / CC);
    float var = s2 * (1.0f / CC) - mean * mean;
    float ln = (v - mean) * rsqrtf(var + 1e-5f) * g[c] + b[c];
    long dst = src_row(r) * CC + c;
    float res = x[dst] + ln;
    g_x1[dst] = res;
    g_x1h[dst] = __float2half_rn(res);
}

// ---------------- final LN(fc2) + residual -> output ----------------
__global__ void final_kernel(float* __restrict__ out,
                             const float* __restrict__ g, const float* __restrict__ b) {
    int r = blockIdx.x;
    int c = threadIdx.x;
    float v = g_pr[(long)r * CC + c];
    float s1 = v, s2 = v * v;
    #pragma unroll
    for (int o = 16; o; o >>= 1) {
        s1 += __shfl_xor_sync(0xffffffffu, s1, o);
        s2 += __shfl_xor_sync(0xffffffffu, s2, o);
    }
    __shared__ float p1[6], p2[6];
    int w = c >> 5;
    if ((c & 31) == 0) { p1[w] = s1; p2[w] = s2; }
    __syncthreads();
    s1 = p1[0] + p1[1] + p1[2] + p1[3] + p1[4] + p1[5];
    s2 = p2[0] + p2[1] + p2[2] + p2[3] + p2[4] + p2[5];
    float mean = s1 * (1.0f / CC);
    float var = s2 * (1.0f / CC) - mean * mean;
    float ln = (v - mean) * rsqrtf(var + 1e-5f) * g[c] + b[c];
    out[(long)r * CC + c] = g_x1[(long)r * CC + c] + ln;
}

// ---------------- launch ----------------
extern "C" void kernel_launch(void* const* d_in, const int* in_sizes, int n_in,
                              void* d_out, int out_size) {
    const float* x      = (const float*)d_in[0];
    const float* qkv_w  = (const float*)d_in[1];
    const float* qkv_b  = (const float*)d_in[2];
    const float* proj_w = (const float*)d_in[3];
    const float* proj_b = (const float*)d_in[4];
    const float* cpb_w1 = (const float*)d_in[5];
    const float* cpb_b1 = (const float*)d_in[6];
    const float* cpb_w2 = (const float*)d_in[7];
    const float* ls     = (const float*)d_in[8];
    const float* n1g    = (const float*)d_in[9];
    const float* n1b    = (const float*)d_in[10];
    const float* n2g    = (const float*)d_in[11];
    const float* n2b    = (const float*)d_in[12];
    const float* fc1_w  = (const float*)d_in[13];
    const float* fc1_b  = (const float*)d_in[14];
    const float* fc2_w  = (const float*)d_in[15];
    const float* fc2_b  = (const float*)d_in[16];
    float* out = (float*)d_out;

    cudaFuncSetAttribute(attn_kernel, cudaFuncAttributeMaxDynamicSharedMemorySize, ATTN_SMEM);

    __half* wq; cudaGetSymbolAddress((void**)&wq, g_wqkv);
    __half* wp; cudaGetSymbolAddress((void**)&wp, g_wproj);
    __half* w1; cudaGetSymbolAddress((void**)&w1, g_wfc1);
    __half* w2; cudaGetSymbolAddress((void**)&w2, g_wfc2);

    conv_kernel<<<(3 * CC * CC + 255) / 256, 256>>>(qkv_w, wq, 3 * CC * CC);
    conv_kernel<<<(CC * CC + 255) / 256, 256>>>(proj_w, wp, CC * CC);
    conv_kernel<<<(HID * CC + 255) / 256, 256>>>(fc1_w, w1, HID * CC);
    conv_kernel<<<(CC * HID + 255) / 256, 256>>>(fc2_w, w2, CC * HID);
    gatherh_kernel<<<(MROWS * 24) / 256, 256>>>(x);
    cpb_kernel<<<CPB_M, CPB_H>>>(cpb_w1, cpb_b1, cpb_w2, ls);

    gemm_qkv_k<<<dim3((3 * CC) / 64, MROWS / 256), 256>>>(qkv_b);
    attn_kernel<<<BWIN * HEADS, 256, ATTN_SMEM>>>();
    gemm_proj_k<<<dim3(CC / 64, MROWS / 256), 256>>>(proj_b);
    attn_post_kernel<<<MROWS, 192>>>(x, n1g, n1b);
    gemm_fc1_k<<<dim3(HID / 64, MROWS / 256), 256>>>(fc1_b);
    gemm_fc2_k<<<dim3(CC / 64, MROWS / 256), 256>>>(fc2_b);
    final_kernel<<<MROWS, 192>>>(out, n2g, n2b);
}